// round 2
// baseline (speedup 1.0000x reference)
#include <cuda_runtime.h>
#include <cuda_fp16.h>
#include <math.h>

// Problem constants
#define Bb   128
#define Nn   96
#define Dd   128
#define Mm   8192
#define KSEL 48
#define MT   128
#define NTILES (Mm / MT)          // 64
#define SCALEF 0.08838834764831845f  // 1/sqrt(128)

// Scratch (static device globals -- allocation-free per harness rules)
__device__ __half g_S[(size_t)Bb * Nn * Mm];         // s logits, fp16 (201 MB)
__device__ float  g_part[(size_t)Bb * Nn * NTILES];  // per-(b,n,tile) partial sum of exp(s)

#define SM_QP  97    // Qs row pad (k-major [128][97])
#define SM_TP  136   // K1 T tile pad (k-major [128][136])
#define SM_XP  97    // K2 x/p tile pad (m-major [128][97])
#define SM_T2P 132   // K2 T tile pad (m-major [128][132])

// ---------------------------------------------------------------------------
// K1: S = Q @ T^T * scale  (per-(tile,b) 96x128 tile)
//     writes fp16 s to g_S and per-row partial sum(exp(s)) to g_part
// ---------------------------------------------------------------------------
__global__ __launch_bounds__(256) void tlp_k1(const float* __restrict__ logits,
                                              const float* __restrict__ tl) {
    extern __shared__ float sm[];
    float* Qs = sm;                        // [128][SM_QP]  (k-major: Qs[k][n])
    float* Ts = sm + 128 * SM_QP;          // [128][SM_TP]  (k-major: Ts[k][m])

    const int b    = blockIdx.y;
    const int tile = blockIdx.x;
    const int tid  = threadIdx.x;
    const int tx   = tid & 15;
    const int ty   = tid >> 4;

    // Load Q_b (96x128) transposed into smem
    const float* qb = logits + (size_t)b * (Nn * Dd);
    for (int e = tid; e < Nn * Dd; e += 256) {
        int n = e >> 7, k = e & 127;
        Qs[k * SM_QP + n] = qb[e];
    }
    // Load T tile (128x128) transposed into smem
    const float* tb = tl + (size_t)tile * MT * Dd;
    for (int e = tid; e < MT * Dd; e += 256) {
        int mm = e >> 7, k = e & 127;
        Ts[k * SM_TP + mm] = tb[e];
    }
    __syncthreads();

    float acc[6][8];
#pragma unroll
    for (int i = 0; i < 6; i++)
#pragma unroll
        for (int j = 0; j < 8; j++) acc[i][j] = 0.f;

    const int sty = 6 * ty;
    // swizzled column assignment: spreads the 16 float4 reads of a warp
    // across bank-quads (was 4-way conflict with plain 8*tx)
    const int stx = 8 * ((tx + 2 * ty) & 15);

#pragma unroll 4
    for (int k = 0; k < 128; k++) {
        float a[6];
#pragma unroll
        for (int i = 0; i < 6; i++) a[i] = Qs[k * SM_QP + sty + i];
        float4 b0 = *(const float4*)(Ts + k * SM_TP + stx);
        float4 b1 = *(const float4*)(Ts + k * SM_TP + stx + 4);
        float bv[8] = {b0.x, b0.y, b0.z, b0.w, b1.x, b1.y, b1.z, b1.w};
#pragma unroll
        for (int i = 0; i < 6; i++)
#pragma unroll
            for (int j = 0; j < 8; j++)
                acc[i][j] = fmaf(a[i], bv[j], acc[i][j]);
    }

    // Epilogue: scale, write fp16 s, accumulate row partial sums of exp(s)
    __half* So = g_S + (size_t)(b * Nn) * Mm + (size_t)tile * MT;
#pragma unroll
    for (int i = 0; i < 6; i++) {
        union { __half h[8]; uint4 u; } pk;
        float es = 0.f;
#pragma unroll
        for (int j = 0; j < 8; j++) {
            float s = acc[i][j] * SCALEF;
            __half hh = __float2half(s);
            pk.h[j] = hh;
            // exp of the quantized value for consistency with K2
            es += __expf(__half2float(hh));
        }
        const int n = sty + i;
        *(uint4*)(So + (size_t)n * Mm + stx) = pk.u;
        // reduce across the 16 tx lanes (segment width 16; permutation of stx
        // within the segment does not change the row sum)
#pragma unroll
        for (int off = 8; off > 0; off >>= 1)
            es += __shfl_down_sync(0xffffffffu, es, off, 16);
        if (tx == 0)
            g_part[((size_t)b * Nn + n) * NTILES + tile] = es;
    }
}

// ---------------------------------------------------------------------------
// K2: persistent per-batch block. For each M-tile:
//   x[m][n] = s - log(rowsum[n]);  per-column (m) find t with count(x>=t)==48;
//   p = exp(x) masked; O[n][d] += P^T @ T.  Finally out = q + O.
// ---------------------------------------------------------------------------
__global__ __launch_bounds__(256) void tlp_k2(const float* __restrict__ logits,
                                              const float* __restrict__ tl,
                                              float* __restrict__ out) {
    extern __shared__ float sm[];
    float* Xt  = sm;                         // [128][SM_XP]   x then p (m-major)
    float* Ts  = sm + 128 * SM_XP;           // [128][SM_T2P]  T tile (m-major)
    float* Ls  = Ts + 128 * SM_T2P;          // [96]  log rowsum
    float* Thr = Ls + Nn;                    // [128] per-column thresholds

    const int b    = blockIdx.x;
    const int tid  = threadIdx.x;
    const int w    = tid >> 5;
    const int lane = tid & 31;

    // Reduce K1 partials -> L[n] = log(rowsum)
    if (tid < Nn) {
        const float* pp = g_part + ((size_t)b * Nn + tid) * NTILES;
        float s = 0.f;
#pragma unroll
        for (int t = 0; t < NTILES; t++) s += pp[t];
        Ls[tid] = logf(s);
    }
    __syncthreads();

    float acc[3][16];
#pragma unroll
    for (int r = 0; r < 3; r++)
#pragma unroll
        for (int c = 0; c < 16; c++) acc[r][c] = 0.f;

    const int rn = 3 * lane;   // each lane owns rows rn..rn+2
    const int cd = 16 * w;     // each warp owns d-range [cd, cd+16)

    const __half* Sb = g_S + (size_t)(b * Nn) * Mm;

    for (int tile = 0; tile < NTILES; tile++) {
        // Load s tile transposed: Xt[m][n] = s - L[n]
        const __half* sp = Sb + (size_t)tile * MT;
        for (int e = tid; e < Nn * MT; e += 256) {
            int n = e >> 7, mm = e & 127;
            Xt[mm * SM_XP + n] = __half2float(sp[(size_t)n * Mm + mm]) - Ls[n];
        }
        // Load T tile (row-major, m-major in smem)
        const float* tb = tl + (size_t)tile * MT * Dd;
        for (int e = tid; e < MT * Dd; e += 256) {
            int mm = e >> 7, d = e & 127;
            Ts[mm * SM_T2P + d] = tb[e];
        }
        __syncthreads();

        // Per-column threshold: warp per column, 96 values in 3 regs/lane.
        for (int c = 0; c < 16; c++) {
            const int mm = w * 16 + c;
            const float* col = Xt + mm * SM_XP;
            float v0 = col[lane], v1 = col[lane + 32], v2 = col[lane + 64];
            float s1 = v0 + v1 + v2;
            float s2 = v0 * v0 + v1 * v1 + v2 * v2;
            float mn = fminf(v0, fminf(v1, v2));
            float mx = fmaxf(v0, fmaxf(v1, v2));
#pragma unroll
            for (int off = 16; off > 0; off >>= 1) {
                s1 += __shfl_xor_sync(0xffffffffu, s1, off);
                s2 += __shfl_xor_sync(0xffffffffu, s2, off);
                mn = fminf(mn, __shfl_xor_sync(0xffffffffu, mn, off));
                mx = fmaxf(mx, __shfl_xor_sync(0xffffffffu, mx, off));
            }
            float mu  = s1 * (1.f / 96.f);
            float sig = sqrtf(fmaxf(s2 * (1.f / 96.f) - mu * mu, 1e-24f));
            float lo = mn, hi = mx, t = mu;
#pragma unroll 1
            for (int it = 0; it < 12; it++) {
                int cnt = __popc(__ballot_sync(0xffffffffu, v0 >= t))
                        + __popc(__ballot_sync(0xffffffffu, v1 >= t))
                        + __popc(__ballot_sync(0xffffffffu, v2 >= t));
                if (cnt >= KSEL) { lo = t; if (cnt == KSEL) break; }
                else hi = t;
                // Newton step using Gaussian density estimate, clipped to bracket
                float tn = t + (float)(cnt - KSEL) * sig * 0.02611f;
                if (!(tn > lo && tn < hi)) tn = 0.5f * (lo + hi);
                t = tn;
            }
            if (lane == 0) Thr[mm] = lo;
        }
        __syncthreads();

        // Masked exp in place: Xt[m][n] = (x >= thr[m]) ? exp(x) : 0
        {
            const int mm = tid >> 1;
            const int nh = (tid & 1) * 48;
            const float th = Thr[mm];
            float* col = Xt + mm * SM_XP + nh;
#pragma unroll
            for (int i = 0; i < 48; i++) {
                float x = col[i];
                col[i] = (x >= th) ? __expf(x) : 0.f;
            }
        }
        __syncthreads();

        // O[n][d] += sum_m p[m][n] * T[m][d]
#pragma unroll 2
        for (int mm = 0; mm < MT; mm++) {
            const float p0 = Xt[mm * SM_XP + rn];
            const float p1 = Xt[mm * SM_XP + rn + 1];
            const float p2 = Xt[mm * SM_XP + rn + 2];
            const float4* tr = (const float4*)(Ts + mm * SM_T2P + cd);
#pragma unroll
            for (int c = 0; c < 4; c++) {
                float4 tv = tr[c];
                acc[0][4 * c + 0] = fmaf(p0, tv.x, acc[0][4 * c + 0]);
                acc[0][4 * c + 1] = fmaf(p0, tv.y, acc[0][4 * c + 1]);
                acc[0][4 * c + 2] = fmaf(p0, tv.z, acc[0][4 * c + 2]);
                acc[0][4 * c + 3] = fmaf(p0, tv.w, acc[0][4 * c + 3]);
                acc[1][4 * c + 0] = fmaf(p1, tv.x, acc[1][4 * c + 0]);
                acc[1][4 * c + 1] = fmaf(p1, tv.y, acc[1][4 * c + 1]);
                acc[1][4 * c + 2] = fmaf(p1, tv.z, acc[1][4 * c + 2]);
                acc[1][4 * c + 3] = fmaf(p1, tv.w, acc[1][4 * c + 3]);
                acc[2][4 * c + 0] = fmaf(p2, tv.x, acc[2][4 * c + 0]);
                acc[2][4 * c + 1] = fmaf(p2, tv.y, acc[2][4 * c + 1]);
                acc[2][4 * c + 2] = fmaf(p2, tv.z, acc[2][4 * c + 2]);
                acc[2][4 * c + 3] = fmaf(p2, tv.w, acc[2][4 * c + 3]);
            }
        }
        __syncthreads();  // protect smem before next tile overwrites
    }

    // Epilogue: out = q + O
    const float* qb = logits + (size_t)b * (Nn * Dd);
    float* ob = out + (size_t)b * (Nn * Dd);
#pragma unroll
    for (int r = 0; r < 3; r++) {
        const int base = (rn + r) * Dd + cd;
#pragma unroll
        for (int c = 0; c < 4; c++) {
            float4 qv = *(const float4*)(qb + base + 4 * c);
            float4 ov;
            ov.x = qv.x + acc[r][4 * c + 0];
            ov.y = qv.y + acc[r][4 * c + 1];
            ov.z = qv.z + acc[r][4 * c + 2];
            ov.w = qv.w + acc[r][4 * c + 3];
            *(float4*)(ob + base + 4 * c) = ov;
        }
    }
}

extern "C" void kernel_launch(void* const* d_in, const int* in_sizes, int n_in,
                              void* d_out, int out_size) {
    const float* logits = (const float*)d_in[0];
    const float* tl     = (const float*)d_in[1];
    float* out          = (float*)d_out;

    const int smem1 = (128 * SM_QP + 128 * SM_TP) * 4;               // 119296 B
    const int smem2 = (128 * SM_XP + 128 * SM_T2P + Nn + 128) * 4;   // 118144 B

    // Idempotent; also applied on the uncaptured correctness call.
    cudaFuncSetAttribute(tlp_k1, cudaFuncAttributeMaxDynamicSharedMemorySize, smem1);
    cudaFuncSetAttribute(tlp_k2, cudaFuncAttributeMaxDynamicSharedMemorySize, smem2);

    tlp_k1<<<dim3(NTILES, Bb), 256, smem1>>>(logits, tl);
    tlp_k2<<<Bb, 256, smem2>>>(logits, tl, out);
}